// round 8
// baseline (speedup 1.0000x reference)
#include <cuda_runtime.h>

// Top-8 of 128 experts per token + softmax over selected logits.
// d_out: [0, T*8) = weights f32; [T*8, 2*T*8) = indices as f32.
//
// One warp processes TWO tokens (A, B). Lane owns 4 contiguous experts
// (float4). In-lane sort in float domain tracking slots; sorted values mapped
// once to order-preserving uint keys; indices ride as packed bytes (head in
// MSB). Per round: REDUX.UMAX over heads -> mr; REDUX.UMIN over
// (head==mr ? pack : ~0) -> cr resolves exact min-index tie-break AND the
// winner's expert index (cr>>24) in one op. Both mr and cr are WARP-UNIFORM,
// so: rank-r value is captured by lane r via one SEL, and the index byte is
// inserted uniformly into a 2-register byte pack via one PRMT — no per-rank
// select trees, no m[]/c[] arrays. Winner lane shifts its sorted list
// (sentinel 0 into the tail). Epilogue: lanes 0-7 emit token A, 8-15 token B;
// softmax via octet-closed xor-shuffle sum.

#define NUM_EXPERTS 128
#define TOPK 8
#define WARPS_PER_BLOCK 8

static __device__ __forceinline__ unsigned ford(float f) {
    int s = __float_as_int(f);
    return (unsigned)(s ^ ((s >> 31) | 0x80000000));
}
static __device__ __forceinline__ float iford(unsigned u) {
    int t = (int)u;
    return __int_as_float(t ^ ((~(t >> 31)) | 0x80000000));
}

struct TokResult {
    unsigned mv;   // this lane's rank-(lane-cap_base) value key (lanes cap_base..+7)
    unsigned m0;   // uniform: max value key (softmax stabilizer)
    unsigned lo;   // uniform: expert indices of ranks 0..3, byte r
    unsigned hi;   // uniform: expert indices of ranks 4..7, byte r-4
};

static __device__ __forceinline__ TokResult
topk_rounds(float4 v4, unsigned lane, unsigned cap_base) {
    float f0 = v4.x, f1 = v4.y, f2 = v4.z, f3 = v4.w;
    unsigned s0, s1, s2, s3;
    {   // CAS(0,1): slots 0,1 -> strict < tie-correct
        bool p = f0 < f1;
        float hi_ = fmaxf(f0, f1), lo_ = fminf(f0, f1);
        f0 = hi_; f1 = lo_; s0 = p ? 1u : 0u; s1 = p ? 0u : 1u;
    }
    {   // CAS(2,3)
        bool p = f2 < f3;
        float hi_ = fmaxf(f2, f3), lo_ = fminf(f2, f3);
        f2 = hi_; f3 = lo_; s2 = p ? 3u : 2u; s3 = p ? 2u : 3u;
    }
    {   // CAS(0,2): slot(pos0)<slot(pos2) always -> ties keep pos0
        bool p = f0 < f2;
        float hi_ = fmaxf(f0, f2), lo_ = fminf(f0, f2);
        f0 = hi_; f2 = lo_;
        unsigned a = p ? s2 : s0, b = p ? s0 : s2; s0 = a; s2 = b;
    }
    {   // CAS(1,3)
        bool p = f1 < f3;
        float hi_ = fmaxf(f1, f3), lo_ = fminf(f1, f3);
        f1 = hi_; f3 = lo_;
        unsigned a = p ? s3 : s1, b = p ? s1 : s3; s1 = a; s3 = b;
    }
    {   // CAS(1,2): only CAS where equal values can arrive slot-misordered
        bool p = (f1 < f2) || (f1 == f2 && s1 > s2);
        float hi_ = fmaxf(f1, f2), lo_ = fminf(f1, f2);
        f1 = hi_; f2 = lo_;
        unsigned a = p ? s2 : s1, b = p ? s1 : s2; s1 = a; s2 = b;
    }

    unsigned k0 = ford(f0), k1 = ford(f1), k2 = ford(f2), k3 = ford(f3);

    unsigned pack = (((((s0 << 8) | s1) << 8) | s2) << 8) | s3;
    pack += lane * 0x04040404u;        // expert base 4*lane in every byte

    // PRMT selectors: dst byte r <- b's byte 3 (MSB of cr), others identity
    const unsigned SEL[4] = {0x3217u, 0x3270u, 0x3710u, 0x7210u};

    TokResult t;
    t.mv = 0u; t.m0 = 0u; t.lo = 0u; t.hi = 0u;

#pragma unroll
    for (int r = 0; r < TOPK; ++r) {
        unsigned mr = __reduce_max_sync(0xffffffffu, k0);
        unsigned cand = (k0 == mr) ? pack : 0xffffffffu;
        unsigned cr = __reduce_min_sync(0xffffffffu, cand);

        if (r == 0) t.m0 = mr;
        t.mv = (lane == cap_base + (unsigned)r) ? mr : t.mv;
        if (r < 4) t.lo = __byte_perm(t.lo, cr, SEL[r]);
        else       t.hi = __byte_perm(t.hi, cr, SEL[r - 4]);

        if (r < TOPK - 1) {
            bool win = (cand == cr);
            k0 = win ? k1 : k0;
            k1 = win ? k2 : k1;
            k2 = win ? k3 : k2;
            k3 = win ? 0u : k3;          // exhausted lane can never re-win
            pack = win ? (pack << 8) : pack;
        }
    }
    return t;
}

__global__ __launch_bounds__(WARPS_PER_BLOCK * 32, 6)
void topk_softmax_kernel(const float* __restrict__ gate,
                         float* __restrict__ out_w,
                         float* __restrict__ out_i,
                         int tokens) {
    const unsigned lane = threadIdx.x & 31;
    const int halfc = (tokens + 1) >> 1;
    const int tA = blockIdx.x * WARPS_PER_BLOCK + (threadIdx.x >> 5);
    if (tA >= halfc) return;
    const int tB = tA + halfc;
    const bool validB = (tB < tokens);

    const float4* g4 = reinterpret_cast<const float4*>(gate);
    const float4 vA = g4[(size_t)tA * (NUM_EXPERTS / 4) + lane];
    float4 vB = make_float4(0.f, 0.f, 0.f, 0.f);
    if (validB) vB = g4[(size_t)tB * (NUM_EXPERTS / 4) + lane];

    const TokResult A = topk_rounds(vA, lane, 0u);
    const TokResult B = topk_rounds(vB, lane, 8u);

    // softmax: lanes 0-7 own token A ranks, lanes 8-15 own token B ranks
    float eA = __expf(iford(A.mv) - iford(A.m0));
    float eB = __expf(iford(B.mv) - iford(B.m0));
    float sA = eA, sB = eB;
    sA += __shfl_xor_sync(0xffffffffu, sA, 1);
    sA += __shfl_xor_sync(0xffffffffu, sA, 2);
    sA += __shfl_xor_sync(0xffffffffu, sA, 4);   // octet-closed
    sB += __shfl_xor_sync(0xffffffffu, sB, 1);
    sB += __shfl_xor_sync(0xffffffffu, sB, 2);
    sB += __shfl_xor_sync(0xffffffffu, sB, 4);
    const float wA = __fdividef(eA, sA);
    const float wB = __fdividef(eB, sB);

    const unsigned rk = lane & 7u;
    const unsigned shamt = (rk & 3u) * 8u;

    if (lane < TOPK) {
        const unsigned idx = ((rk < 4u ? A.lo : A.hi) >> shamt) & 0xffu;
        const size_t o = (size_t)tA * TOPK + rk;
        out_w[o] = wA;
        out_i[o] = (float)idx;
    } else if (lane < 2u * TOPK && validB) {
        const unsigned idx = ((rk < 4u ? B.lo : B.hi) >> shamt) & 0xffu;
        const size_t o = (size_t)tB * TOPK + rk;
        out_w[o] = wB;
        out_i[o] = (float)idx;
    }
}

extern "C" void kernel_launch(void* const* d_in, const int* in_sizes, int n_in,
                              void* d_out, int out_size) {
    (void)n_in; (void)out_size;
    const float* gate = (const float*)d_in[0];
    const int tokens = in_sizes[0] / NUM_EXPERTS;

    float* out_w = (float*)d_out;
    float* out_i = out_w + (size_t)tokens * TOPK;

    const int halfc = (tokens + 1) >> 1;
    const int blocks = (halfc + WARPS_PER_BLOCK - 1) / WARPS_PER_BLOCK;
    topk_softmax_kernel<<<blocks, WARPS_PER_BLOCK * 32>>>(gate, out_w, out_i, tokens);
}